// round 1
// baseline (speedup 1.0000x reference)
#include <cuda_runtime.h>

#define B_     8
#define NA_    9
#define NH_    64
#define NW_    64
#define NG_    32
#define NC_    80
#define NANCH  (NA_*NH_*NW_)        // 36864
#define TPB    256
#define BPI    (NANCH/TPB)          // 144 blocks per image
#define NBLK   (B_*BPI)             // 1152

// per-block partials (deterministic reduction, no atomics)
__device__ float g_cls [NBLK];
__device__ float g_xywh[NBLK];
__device__ float g_npos[NBLK];

// anchor w/h: base=32, scales {1, 1.2599, 1.5874}, ratios {(1,1),(1.4,0.7),(0.7,1.4)}
// computed in double then cast to float, matching jnp float64->float32
__constant__ float c_aw[9] = {
    (float)(32.0*1.0),        (float)(32.0*1.0*1.4),        (float)(32.0*1.0*0.7),
    (float)(32.0*1.2599),     (float)(32.0*1.2599*1.4),     (float)(32.0*1.2599*0.7),
    (float)(32.0*1.5874),     (float)(32.0*1.5874*1.4),     (float)(32.0*1.5874*0.7)
};
__constant__ float c_ah[9] = {
    (float)(32.0*1.0),        (float)(32.0*1.0*0.7),        (float)(32.0*1.0*1.4),
    (float)(32.0*1.2599),     (float)(32.0*1.2599*0.7),     (float)(32.0*1.2599*1.4),
    (float)(32.0*1.5874),     (float)(32.0*1.5874*0.7),     (float)(32.0*1.5874*1.4)
};

__device__ __forceinline__ float ex2f(float x) {
    float y; asm("ex2.approx.f32 %0, %1;" : "=f"(y) : "f"(x)); return y;
}
__device__ __forceinline__ float lg2f(float x) {
    float y; asm("lg2.approx.f32 %0, %1;" : "=f"(y) : "f"(x)); return y;
}

__global__ void __launch_bounds__(TPB)
retina_main(const float* __restrict__ t_xywh,
            const float* __restrict__ logits,
            const float* __restrict__ gtb,
            const int*   __restrict__ gtc)
{
    __shared__ float4 s_tlbr[NG_];   // tlx,tly,brx,bry
    __shared__ float4 s_box [NG_];   // cx,cy,w,h
    __shared__ float  s_area[NG_];
    __shared__ int    s_cat [NG_];
    __shared__ float  s_red[3][8];

    const int bid = blockIdx.x;
    const int b   = bid / BPI;
    const int blk = bid % BPI;
    const int tid = threadIdx.x;

    if (tid < NG_) {
        float4 g = ((const float4*)gtb)[b*NG_ + tid];
        float hw = 0.5f*g.z, hh = 0.5f*g.w;
        s_tlbr[tid] = make_float4(g.x - hw, g.y - hh, g.x + hw, g.y + hh);
        s_box [tid] = g;
        s_area[tid] = g.z * g.w;
        s_cat [tid] = gtc[b*NG_ + tid];
    }
    __syncthreads();

    const int n = blk*TPB + tid;        // anchor index within image: a*4096 + h*64 + w
    const int a = n >> 12;
    const int h = (n >> 6) & 63;
    const int w = n & 63;

    const float aw = c_aw[a], ah = c_ah[a];
    const float acx = ((float)w + 0.5f) * 8.0f;
    const float acy = ((float)h + 0.5f) * 8.0f;
    const float atlx = acx - 0.5f*aw, atly = acy - 0.5f*ah;
    const float abrx = acx + 0.5f*aw, abry = acy + 0.5f*ah;
    const float areaA = aw * ah;

    // best IoU tracked as (I, U) pair: compare via cross-multiplication, no division
    float bI = 0.0f, bU = 1.0f;
    int   bG = 0;
    #pragma unroll 8
    for (int g = 0; g < NG_; ++g) {
        float4 t = s_tlbr[g];
        float ox = fminf(abrx, t.z) - fmaxf(atlx, t.x);
        float oy = fminf(abry, t.w) - fmaxf(atly, t.y);
        ox = fmaxf(ox, 0.0f);
        oy = fmaxf(oy, 0.0f);
        float I = ox * oy;
        float U = (areaA - I) + s_area[g];
        if (I * bU > bI * U) { bI = I; bU = U; bG = g; }
    }

    const bool pos = bI > 0.5f * bU;
    const bool neg = bI < 0.4f * bU;

    // regression loss (rare: pos anchors only)
    float l_xywh = 0.0f;
    if (pos) {
        float4 g = s_box[bG];
        float tx = (g.x - acx) / aw;
        float ty = (g.y - acy) / ah;
        float tw = __logf(g.z / aw + 1e-8f);
        float th = __logf(g.w / ah + 1e-8f);
        float4 t = ((const float4*)t_xywh)[ ((b*NA_ + a) << 12) + (h << 6) + w ];
        float dx = t.x - tx, dy = t.y - ty, dw = t.z - tw, dh = t.w - th;
        l_xywh = dx*dx + dy*dy + dw*dw + dh*dh;
    }

    // classification BCE over 80 logits.
    // softplus(x) = max(x,0) + log1p(exp(-|x|)); batch 16 (1+y) factors into one
    // product, one lg2 per 16 elements (product in [1, 2^16], safe in f32).
    float acc_cls = 0.0f;
    if (pos | neg) {
        const int tc = pos ? s_cat[bG] : -1;
        const float4* lp = (const float4*)logits
                         + (size_t)(((b*NA_ + a) << 12) + (h << 6) + w) * (NC_/4);
        float acc_r = 0.0f, acc_l = 0.0f, p = 1.0f;
        #pragma unroll
        for (int i = 0; i < NC_/4; ++i) {
            float4 v = lp[i];
            #define PROC(X, CIDX) { \
                float xx = (X); \
                float yy = ex2f(-1.4426950408889634f * fabsf(xx)); \
                p = __fmaf_rn(p, yy, p); \
                acc_r += fmaxf(xx, 0.0f); \
                if ((CIDX) == tc) acc_r -= xx; }
            PROC(v.x, 4*i + 0)
            PROC(v.y, 4*i + 1)
            PROC(v.z, 4*i + 2)
            PROC(v.w, 4*i + 3)
            #undef PROC
            if ((i & 3) == 3) { acc_l += lg2f(p); p = 1.0f; }
        }
        acc_cls = acc_r + 0.6931471805599453f * acc_l;
    }

    // block reduction of (cls, xywh, npos)
    float v0 = acc_cls, v1 = l_xywh, v2 = pos ? 1.0f : 0.0f;
    #pragma unroll
    for (int o = 16; o; o >>= 1) {
        v0 += __shfl_down_sync(0xFFFFFFFFu, v0, o);
        v1 += __shfl_down_sync(0xFFFFFFFFu, v1, o);
        v2 += __shfl_down_sync(0xFFFFFFFFu, v2, o);
    }
    const int lane = tid & 31, wrp = tid >> 5;
    if (lane == 0) { s_red[0][wrp] = v0; s_red[1][wrp] = v1; s_red[2][wrp] = v2; }
    __syncthreads();
    if (wrp == 0 && lane < 8) {
        v0 = s_red[0][lane]; v1 = s_red[1][lane]; v2 = s_red[2][lane];
        #pragma unroll
        for (int o = 4; o; o >>= 1) {
            v0 += __shfl_down_sync(0x000000FFu, v0, o);
            v1 += __shfl_down_sync(0x000000FFu, v1, o);
            v2 += __shfl_down_sync(0x000000FFu, v2, o);
        }
        if (lane == 0) { g_cls[bid] = v0; g_xywh[bid] = v1; g_npos[bid] = v2; }
    }
}

__global__ void __launch_bounds__(TPB)
retina_final(float* __restrict__ out)
{
    __shared__ float sm_x[8];
    __shared__ float sm_c[8];
    const int tid  = threadIdx.x;
    const int lane = tid & 31, wrp = tid >> 5;

    // global xywh sum over all 1152 partials
    float sx = 0.0f;
    for (int i = tid; i < NBLK; i += TPB) sx += g_xywh[i];
    #pragma unroll
    for (int o = 16; o; o >>= 1) sx += __shfl_down_sync(0xFFFFFFFFu, sx, o);
    if (lane == 0) sm_x[wrp] = sx;

    // per-image cls sum / (npos+1): warp `wrp` handles image `wrp`
    float sc = 0.0f, sp = 0.0f;
    for (int i = lane; i < BPI; i += 32) {
        sc += g_cls [wrp*BPI + i];
        sp += g_npos[wrp*BPI + i];
    }
    #pragma unroll
    for (int o = 16; o; o >>= 1) {
        sc += __shfl_down_sync(0xFFFFFFFFu, sc, o);
        sp += __shfl_down_sync(0xFFFFFFFFu, sp, o);
    }
    if (lane == 0) sm_c[wrp] = sc / (sp + 1.0f);
    __syncthreads();

    if (tid == 0) {
        float tot = 0.0f;
        #pragma unroll
        for (int i = 0; i < 8; ++i) tot += sm_x[i] + sm_c[i];
        out[0] = tot * (1.0f / (float)B_);
    }
}

extern "C" void kernel_launch(void* const* d_in, const int* in_sizes, int n_in,
                              void* d_out, int out_size)
{
    const float* t_xywh = (const float*)d_in[0];
    const float* logits = (const float*)d_in[1];
    const float* gtb    = (const float*)d_in[2];
    const int*   gtc    = (const int*)  d_in[3];
    (void)in_sizes; (void)n_in; (void)out_size;

    retina_main <<<NBLK, TPB>>>(t_xywh, logits, gtb, gtc);
    retina_final<<<1, TPB>>>((float*)d_out);
}

// round 2
// speedup vs baseline: 1.0553x; 1.0553x over previous
#include <cuda_runtime.h>

#define B_     8
#define NA_    9
#define NH_    64
#define NW_    64
#define NG_    32
#define NC_    80
#define NANCH  (NA_*NH_*NW_)        // 36864
#define TPB    256
#define BPI    (NANCH/TPB)          // 144 blocks per image
#define NBLK   (B_*BPI)             // 1152

// per-block partials (deterministic reduction, no atomics)
__device__ float g_cls [NBLK];
__device__ float g_xywh[NBLK];
__device__ float g_npos[NBLK];

// anchor w/h: base=32, scales {1, 1.2599, 1.5874}, ratios {(1,1),(1.4,0.7),(0.7,1.4)}
// computed in double then cast to float, matching jnp float64->float32
__constant__ float c_aw[9] = {
    (float)(32.0*1.0),        (float)(32.0*1.0*1.4),        (float)(32.0*1.0*0.7),
    (float)(32.0*1.2599),     (float)(32.0*1.2599*1.4),     (float)(32.0*1.2599*0.7),
    (float)(32.0*1.5874),     (float)(32.0*1.5874*1.4),     (float)(32.0*1.5874*0.7)
};
__constant__ float c_ah[9] = {
    (float)(32.0*1.0),        (float)(32.0*1.0*0.7),        (float)(32.0*1.0*1.4),
    (float)(32.0*1.2599),     (float)(32.0*1.2599*0.7),     (float)(32.0*1.2599*1.4),
    (float)(32.0*1.5874),     (float)(32.0*1.5874*0.7),     (float)(32.0*1.5874*1.4)
};

__device__ __forceinline__ float ex2f(float x) {
    float y; asm("ex2.approx.f32 %0, %1;" : "=f"(y) : "f"(x)); return y;
}
__device__ __forceinline__ float lg2f(float x) {
    float y; asm("lg2.approx.f32 %0, %1;" : "=f"(y) : "f"(x)); return y;
}

__global__ void __launch_bounds__(TPB)
retina_main(const float* __restrict__ t_xywh,
            const float* __restrict__ logits,
            const float* __restrict__ gtb,
            const int*   __restrict__ gtc)
{
    __shared__ float4 s_tlbr[NG_];   // tlx,tly,brx,bry
    __shared__ float4 s_box [NG_];   // cx,cy,w,h
    __shared__ float  s_area[NG_];
    __shared__ int    s_cat [NG_];
    __shared__ float  s_red[3][8];

    const int bid = blockIdx.x;
    const int b   = bid / BPI;
    const int blk = bid % BPI;
    const int tid = threadIdx.x;

    if (tid < NG_) {
        float4 g = ((const float4*)gtb)[b*NG_ + tid];
        float hw = 0.5f*g.z, hh = 0.5f*g.w;
        s_tlbr[tid] = make_float4(g.x - hw, g.y - hh, g.x + hw, g.y + hh);
        s_box [tid] = g;
        s_area[tid] = g.z * g.w;
        s_cat [tid] = gtc[b*NG_ + tid];
    }
    __syncthreads();

    const int n = blk*TPB + tid;        // anchor index within image: a*4096 + h*64 + w
    const int a = n >> 12;
    const int h = (n >> 6) & 63;
    const int w = n & 63;

    const float aw = c_aw[a], ah = c_ah[a];
    const float acx = ((float)w + 0.5f) * 8.0f;
    const float acy = ((float)h + 0.5f) * 8.0f;
    const float atlx = acx - 0.5f*aw, atly = acy - 0.5f*ah;
    const float abrx = acx + 0.5f*aw, abry = acy + 0.5f*ah;
    const float areaA = aw * ah;

    // best IoU tracked as (I, U) pair: compare via cross-multiplication, no division
    float bI = 0.0f, bU = 1.0f;
    int   bG = 0;
    #pragma unroll 8
    for (int g = 0; g < NG_; ++g) {
        float4 t = s_tlbr[g];
        float ox = fminf(abrx, t.z) - fmaxf(atlx, t.x);
        float oy = fminf(abry, t.w) - fmaxf(atly, t.y);
        ox = fmaxf(ox, 0.0f);
        oy = fmaxf(oy, 0.0f);
        float I = ox * oy;
        float U = (areaA - I) + s_area[g];
        if (I * bU > bI * U) { bI = I; bU = U; bG = g; }
    }

    const bool pos = bI > 0.5f * bU;
    const bool neg = bI < 0.4f * bU;

    // regression loss (rare: pos anchors only)
    float l_xywh = 0.0f;
    if (pos) {
        float4 g = s_box[bG];
        float tx = (g.x - acx) / aw;
        float ty = (g.y - acy) / ah;
        float tw = __logf(g.z / aw + 1e-8f);
        float th = __logf(g.w / ah + 1e-8f);
        float4 t = ((const float4*)t_xywh)[ ((b*NA_ + a) << 12) + (h << 6) + w ];
        float dx = t.x - tx, dy = t.y - ty, dw = t.z - tw, dh = t.w - th;
        l_xywh = dx*dx + dy*dy + dw*dw + dh*dh;
    }

    // classification BCE over 80 logits.
    // softplus(x) = max(x,0) + log1p(exp(-|x|)); batch 16 (1+y) factors into one
    // product, one lg2 per 16 elements (product in [1, 2^16], safe in f32).
    float acc_cls = 0.0f;
    if (pos | neg) {
        const int tc = pos ? s_cat[bG] : -1;
        const float4* lp = (const float4*)logits
                         + (size_t)(((b*NA_ + a) << 12) + (h << 6) + w) * (NC_/4);
        float acc_r = 0.0f, acc_l = 0.0f, p = 1.0f;
        #pragma unroll
        for (int i = 0; i < NC_/4; ++i) {
            float4 v = lp[i];
            #define PROC(X, CIDX) { \
                float xx = (X); \
                float yy = ex2f(-1.4426950408889634f * fabsf(xx)); \
                p = __fmaf_rn(p, yy, p); \
                acc_r += fmaxf(xx, 0.0f); \
                if ((CIDX) == tc) acc_r -= xx; }
            PROC(v.x, 4*i + 0)
            PROC(v.y, 4*i + 1)
            PROC(v.z, 4*i + 2)
            PROC(v.w, 4*i + 3)
            #undef PROC
            if ((i & 3) == 3) { acc_l += lg2f(p); p = 1.0f; }
        }
        acc_cls = acc_r + 0.6931471805599453f * acc_l;
    }

    // block reduction of (cls, xywh, npos)
    float v0 = acc_cls, v1 = l_xywh, v2 = pos ? 1.0f : 0.0f;
    #pragma unroll
    for (int o = 16; o; o >>= 1) {
        v0 += __shfl_down_sync(0xFFFFFFFFu, v0, o);
        v1 += __shfl_down_sync(0xFFFFFFFFu, v1, o);
        v2 += __shfl_down_sync(0xFFFFFFFFu, v2, o);
    }
    const int lane = tid & 31, wrp = tid >> 5;
    if (lane == 0) { s_red[0][wrp] = v0; s_red[1][wrp] = v1; s_red[2][wrp] = v2; }
    __syncthreads();
    if (wrp == 0 && lane < 8) {
        v0 = s_red[0][lane]; v1 = s_red[1][lane]; v2 = s_red[2][lane];
        #pragma unroll
        for (int o = 4; o; o >>= 1) {
            v0 += __shfl_down_sync(0x000000FFu, v0, o);
            v1 += __shfl_down_sync(0x000000FFu, v1, o);
            v2 += __shfl_down_sync(0x000000FFu, v2, o);
        }
        if (lane == 0) { g_cls[bid] = v0; g_xywh[bid] = v1; g_npos[bid] = v2; }
    }
}

__global__ void __launch_bounds__(TPB)
retina_final(float* __restrict__ out)
{
    __shared__ float sm_x[8];
    __shared__ float sm_c[8];
    const int tid  = threadIdx.x;
    const int lane = tid & 31, wrp = tid >> 5;

    // global xywh sum over all 1152 partials
    float sx = 0.0f;
    for (int i = tid; i < NBLK; i += TPB) sx += g_xywh[i];
    #pragma unroll
    for (int o = 16; o; o >>= 1) sx += __shfl_down_sync(0xFFFFFFFFu, sx, o);
    if (lane == 0) sm_x[wrp] = sx;

    // per-image cls sum / (npos+1): warp `wrp` handles image `wrp`
    float sc = 0.0f, sp = 0.0f;
    for (int i = lane; i < BPI; i += 32) {
        sc += g_cls [wrp*BPI + i];
        sp += g_npos[wrp*BPI + i];
    }
    #pragma unroll
    for (int o = 16; o; o >>= 1) {
        sc += __shfl_down_sync(0xFFFFFFFFu, sc, o);
        sp += __shfl_down_sync(0xFFFFFFFFu, sp, o);
    }
    if (lane == 0) sm_c[wrp] = sc / (sp + 1.0f);
    __syncthreads();

    if (tid == 0) {
        float tot = 0.0f;
        #pragma unroll
        for (int i = 0; i < 8; ++i) tot += sm_x[i] + sm_c[i];
        out[0] = tot * (1.0f / (float)B_);
    }
}

extern "C" void kernel_launch(void* const* d_in, const int* in_sizes, int n_in,
                              void* d_out, int out_size)
{
    const float* t_xywh = (const float*)d_in[0];
    const float* logits = (const float*)d_in[1];
    const float* gtb    = (const float*)d_in[2];
    const int*   gtc    = (const int*)  d_in[3];
    (void)in_sizes; (void)n_in; (void)out_size;

    retina_main <<<NBLK, TPB>>>(t_xywh, logits, gtb, gtc);
    retina_final<<<1, TPB>>>((float*)d_out);
}

// round 3
// speedup vs baseline: 1.2578x; 1.1919x over previous
#include <cuda_runtime.h>

#define B_     8
#define NA_    9
#define NH_    64
#define NW_    64
#define NG_    32
#define NC_    80
#define NANCH  (NA_*NH_*NW_)        // 36864
#define TPB    256
#define BPI    (NANCH/TPB)          // 144 blocks per image
#define NBLK   (B_*BPI)             // 1152

// per-block partials (deterministic reduction, no atomics on floats)
__device__ float g_cls [NBLK];
__device__ float g_xywh[NBLK];
__device__ float g_npos[NBLK];
__device__ unsigned int g_count = 0;   // last-block-done counter (reset each run)

// anchor w/h: base=32, scales {1, 1.2599, 1.5874}, ratios {(1,1),(1.4,0.7),(0.7,1.4)}
__constant__ float c_aw[9] = {
    (float)(32.0*1.0),        (float)(32.0*1.0*1.4),        (float)(32.0*1.0*0.7),
    (float)(32.0*1.2599),     (float)(32.0*1.2599*1.4),     (float)(32.0*1.2599*0.7),
    (float)(32.0*1.5874),     (float)(32.0*1.5874*1.4),     (float)(32.0*1.5874*0.7)
};
__constant__ float c_ah[9] = {
    (float)(32.0*1.0),        (float)(32.0*1.0*0.7),        (float)(32.0*1.0*1.4),
    (float)(32.0*1.2599),     (float)(32.0*1.2599*0.7),     (float)(32.0*1.2599*1.4),
    (float)(32.0*1.5874),     (float)(32.0*1.5874*0.7),     (float)(32.0*1.5874*1.4)
};

__device__ __forceinline__ float ex2f(float x) {
    float y; asm("ex2.approx.f32 %0, %1;" : "=f"(y) : "f"(x)); return y;
}
__device__ __forceinline__ float lg2f(float x) {
    float y; asm("lg2.approx.f32 %0, %1;" : "=f"(y) : "f"(x)); return y;
}

__global__ void __launch_bounds__(TPB)
retina_fused(const float* __restrict__ t_xywh,
             const float* __restrict__ logits,
             const float* __restrict__ gtb,
             const int*   __restrict__ gtc,
             float* __restrict__ out)
{
    __shared__ float4 s_tlbr[NG_];   // tlx,tly,brx,bry
    __shared__ float4 s_box [NG_];   // cx,cy,w,h
    __shared__ float  s_area[NG_];
    __shared__ int    s_cat [NG_];
    __shared__ float  s_penf[TPB];   // per-anchor penalty flag (0/1)
    __shared__ float  s_red[3][8];
    __shared__ float  s_fin[16];
    __shared__ unsigned int s_last;

    const int bid = blockIdx.x;
    const int b   = bid / BPI;
    const int blk = bid % BPI;
    const int tid = threadIdx.x;

    if (tid < NG_) {
        float4 g = ((const float4*)gtb)[b*NG_ + tid];
        float hw = 0.5f*g.z, hh = 0.5f*g.w;
        s_tlbr[tid] = make_float4(g.x - hw, g.y - hh, g.x + hw, g.y + hh);
        s_box [tid] = g;
        s_area[tid] = g.z * g.w;
        s_cat [tid] = gtc[b*NG_ + tid];
    }
    __syncthreads();

    // ---- phase 1: per-anchor IoU argmax, pos/neg, regression loss ----
    const int n = blk*TPB + tid;        // anchor index within image: a*4096 + h*64 + w
    const int a = n >> 12;
    const int h = (n >> 6) & 63;
    const int w = n & 63;

    const float aw = c_aw[a], ah = c_ah[a];
    const float acx = ((float)w + 0.5f) * 8.0f;
    const float acy = ((float)h + 0.5f) * 8.0f;
    const float atlx = acx - 0.5f*aw, atly = acy - 0.5f*ah;
    const float abrx = acx + 0.5f*aw, abry = acy + 0.5f*ah;
    const float areaA = aw * ah;

    // best IoU tracked as (I, U) pair: cross-multiplied compare, no division
    float bI = 0.0f, bU = 1.0f;
    int   bG = 0;
    #pragma unroll 8
    for (int g = 0; g < NG_; ++g) {
        float4 t = s_tlbr[g];
        float ox = fminf(abrx, t.z) - fmaxf(atlx, t.x);
        float oy = fminf(abry, t.w) - fmaxf(atly, t.y);
        ox = fmaxf(ox, 0.0f);
        oy = fmaxf(oy, 0.0f);
        float I = ox * oy;
        float U = (areaA - I) + s_area[g];
        if (I * bU > bI * U) { bI = I; bU = U; bG = g; }
    }

    const bool pos = bI > 0.5f * bU;
    const bool neg = bI < 0.4f * bU;

    float l_xywh = 0.0f;
    float sub    = 0.0f;     // one-hot -x[tc] term (pos anchors only)
    if (pos) {
        float4 g = s_box[bG];
        float tx = (g.x - acx) / aw;
        float ty = (g.y - acy) / ah;
        float tw = __logf(g.z / aw + 1e-8f);
        float th = __logf(g.w / ah + 1e-8f);
        float4 t = ((const float4*)t_xywh)[ (size_t)((b*NA_ + a) << 12) + (h << 6) + w ];
        float dx = t.x - tx, dy = t.y - ty, dw = t.z - tw, dh = t.w - th;
        l_xywh = dx*dx + dy*dy + dw*dw + dh*dh;
        sub = logits[(size_t)(b*NANCH + n)*NC_ + s_cat[bG]];
    }

    s_penf[tid] = (pos | neg) ? 1.0f : 0.0f;
    __syncthreads();

    // ---- phase 2: block-cooperative, coalesced BCE over 256 anchors x 80 classes ----
    // softplus(x) = max(x,0) + log1p(exp(-|x|)); batch 16 (1+y) factors into one
    // product, one lg2 per 16 elements (product in [1, 2^16], safe in f32).
    const float4* lp = (const float4*)logits + (size_t)(b*NANCH + blk*TPB)*(NC_/4);
    float acc_r = -sub, acc_l = 0.0f, p = 1.0f;
    #pragma unroll
    for (int k = 0; k < 5*TPB*4/256; ++k) {   // 20 iterations
        const int idx4   = tid + k*TPB;       // 0..5119
        const int anchor = idx4 / (NC_/4);    // local anchor 0..255
        const float pen  = s_penf[anchor];
        float4 v = lp[idx4];
        {   float y;
            y = ex2f(-1.4426950408889634f * fabsf(v.x));
            p = __fmaf_rn(p, y*pen, p);
            acc_r = __fmaf_rn(pen, fmaxf(v.x, 0.0f), acc_r);
            y = ex2f(-1.4426950408889634f * fabsf(v.y));
            p = __fmaf_rn(p, y*pen, p);
            acc_r = __fmaf_rn(pen, fmaxf(v.y, 0.0f), acc_r);
            y = ex2f(-1.4426950408889634f * fabsf(v.z));
            p = __fmaf_rn(p, y*pen, p);
            acc_r = __fmaf_rn(pen, fmaxf(v.z, 0.0f), acc_r);
            y = ex2f(-1.4426950408889634f * fabsf(v.w));
            p = __fmaf_rn(p, y*pen, p);
            acc_r = __fmaf_rn(pen, fmaxf(v.w, 0.0f), acc_r);
        }
        if ((k & 3) == 3) { acc_l += lg2f(p); p = 1.0f; }
    }
    float acc_cls = acc_r + 0.6931471805599453f * acc_l;

    // ---- block reduction of (cls, xywh, npos) ----
    float v0 = acc_cls, v1 = l_xywh, v2 = pos ? 1.0f : 0.0f;
    #pragma unroll
    for (int o = 16; o; o >>= 1) {
        v0 += __shfl_down_sync(0xFFFFFFFFu, v0, o);
        v1 += __shfl_down_sync(0xFFFFFFFFu, v1, o);
        v2 += __shfl_down_sync(0xFFFFFFFFu, v2, o);
    }
    const int lane = tid & 31, wrp = tid >> 5;
    if (lane == 0) { s_red[0][wrp] = v0; s_red[1][wrp] = v1; s_red[2][wrp] = v2; }
    __syncthreads();
    if (wrp == 0 && lane < 8) {
        v0 = s_red[0][lane]; v1 = s_red[1][lane]; v2 = s_red[2][lane];
        #pragma unroll
        for (int o = 4; o; o >>= 1) {
            v0 += __shfl_down_sync(0x000000FFu, v0, o);
            v1 += __shfl_down_sync(0x000000FFu, v1, o);
            v2 += __shfl_down_sync(0x000000FFu, v2, o);
        }
        if (lane == 0) { g_cls[bid] = v0; g_xywh[bid] = v1; g_npos[bid] = v2; }
    }
    __syncthreads();

    // ---- last-block-done: final deterministic reduction, no 2nd launch ----
    if (tid == 0) {
        __threadfence();
        s_last = (atomicAdd(&g_count, 1u) == NBLK - 1u);
    }
    __syncthreads();
    if (!s_last) return;
    __threadfence();

    // global xywh sum over all 1152 partials (fixed order -> deterministic)
    float sx = 0.0f;
    for (int i = tid; i < NBLK; i += TPB) sx += __ldcg(&g_xywh[i]);
    #pragma unroll
    for (int o = 16; o; o >>= 1) sx += __shfl_down_sync(0xFFFFFFFFu, sx, o);
    if (lane == 0) s_fin[wrp] = sx;

    // per-image cls sum / (npos+1): warp `wrp` handles image `wrp`
    float sc = 0.0f, sp = 0.0f;
    for (int i = lane; i < BPI; i += 32) {
        sc += __ldcg(&g_cls [wrp*BPI + i]);
        sp += __ldcg(&g_npos[wrp*BPI + i]);
    }
    #pragma unroll
    for (int o = 16; o; o >>= 1) {
        sc += __shfl_down_sync(0xFFFFFFFFu, sc, o);
        sp += __shfl_down_sync(0xFFFFFFFFu, sp, o);
    }
    if (lane == 0) s_fin[8 + wrp] = sc / (sp + 1.0f);
    __syncthreads();

    if (tid == 0) {
        float tot = 0.0f;
        #pragma unroll
        for (int i = 0; i < 16; ++i) tot += s_fin[i];
        out[0] = tot * (1.0f / (float)B_);
        g_count = 0;   // reset for next graph replay
    }
}

extern "C" void kernel_launch(void* const* d_in, const int* in_sizes, int n_in,
                              void* d_out, int out_size)
{
    const float* t_xywh = (const float*)d_in[0];
    const float* logits = (const float*)d_in[1];
    const float* gtb    = (const float*)d_in[2];
    const int*   gtc    = (const int*)  d_in[3];
    (void)in_sizes; (void)n_in; (void)out_size;

    retina_fused<<<NBLK, TPB>>>(t_xywh, logits, gtb, gtc, (float*)d_out);
}